// round 2
// baseline (speedup 1.0000x reference)
#include <cuda_runtime.h>

// Problem constants
#define Bc 4
#define Tc 4096
#define Ec 2048
#define Hc 16
#define Dc 128
#define NR (Bc * Tc)          // 16384 rows
#define TSPLIT 8
#define TCHUNK (Tc / TSPLIT)  // 512

// Scratch (device globals: allocation-free per harness rules)
__device__ float g_Q[(size_t)NR * Ec];
__device__ float g_K[(size_t)NR * Ec];
__device__ float g_V[(size_t)NR * Ec];
__device__ float g_attn[(size_t)NR * Ec];
__device__ float g_KVp[(size_t)TSPLIT * Bc * Hc * Dc * Dc];  // partial KV per T-chunk
__device__ float g_KV[(size_t)Bc * Hc * Dc * Dc];

// ---------------------------------------------------------------------------
// Packed f32x2 helpers (Blackwell sm_103a dual-rate fp32 path)
// ---------------------------------------------------------------------------
__device__ __forceinline__ unsigned long long bcast2(float x) {
    unsigned long long r;
    asm("mov.b64 %0, {%1, %1};" : "=l"(r) : "f"(x));
    return r;
}
__device__ __forceinline__ void fma2(unsigned long long& d,
                                     unsigned long long a,
                                     unsigned long long b) {
    asm("fma.rn.f32x2 %0, %1, %2, %0;" : "+l"(d) : "l"(a), "l"(b));
}
__device__ __forceinline__ float2 unpack2(unsigned long long v) {
    float2 f;
    asm("mov.b64 {%0, %1}, %2;" : "=f"(f.x), "=f"(f.y) : "l"(v));
    return f;
}

// Shared-tile microkernel: acc[8][4 packed pairs] += As-col-frag ⊗ Bs-row-frag
// As, Bs: [16][128], As stores the "row" operand transposed (As[k][m]).
__device__ __forceinline__ void mma16(const float (*As)[128], const float (*Bs)[128],
                                      unsigned long long (&acc)[8][4],
                                      int tx, int ty) {
    #pragma unroll
    for (int kk = 0; kk < 16; kk++) {
        const float4 a0 = *(const float4*)&As[kk][ty * 8];
        const float4 a1 = *(const float4*)&As[kk][ty * 8 + 4];
        const ulonglong2 u = *(const ulonglong2*)&Bs[kk][tx * 8];
        const ulonglong2 v = *(const ulonglong2*)&Bs[kk][tx * 8 + 4];
        const unsigned long long pb0 = u.x, pb1 = u.y, pb2 = v.x, pb3 = v.y;
        const float aa[8] = {a0.x, a0.y, a0.z, a0.w, a1.x, a1.y, a1.z, a1.w};
        #pragma unroll
        for (int i = 0; i < 8; i++) {
            const unsigned long long pa = bcast2(aa[i]);
            fma2(acc[i][0], pa, pb0);
            fma2(acc[i][1], pa, pb1);
            fma2(acc[i][2], pa, pb2);
            fma2(acc[i][3], pa, pb3);
        }
    }
}

// ---------------------------------------------------------------------------
// Generic C = A @ W^T + bias   (A: [M,K] row-major, W: [N,K] row-major)
// 128x128 block tile, BK=16, 256 threads, 8x8 per-thread microtile (packed).
// ---------------------------------------------------------------------------
__global__ __launch_bounds__(256, 2) void gemm_nt_bias(
    const float* __restrict__ A, const float* __restrict__ W,
    const float* __restrict__ bias, float* __restrict__ C,
    int M, int N, int K)
{
    __shared__ __align__(16) float As[16][128];
    __shared__ __align__(16) float Bs[16][128];

    const int tid = threadIdx.x;
    const int tx = tid & 15;   // 0..15 col group
    const int ty = tid >> 4;   // 0..15 row group
    const int rowBase = blockIdx.y * 128;
    const int colBase = blockIdx.x * 128;

    // Load mapping: 512 float4 per tile, 2 per thread
    const int r0 = tid >> 2;          // 0..63
    const int c0 = (tid & 3) * 4;     // 0,4,8,12
    const int r1 = r0 + 64;

    const float* Ar0 = A + (size_t)(rowBase + r0) * K + c0;
    const float* Ar1 = A + (size_t)(rowBase + r1) * K + c0;
    const float* Wr0 = W + (size_t)(colBase + r0) * K + c0;
    const float* Wr1 = W + (size_t)(colBase + r1) * K + c0;

    unsigned long long acc[8][4] = {};

    for (int k0 = 0; k0 < K; k0 += 16) {
        float4 a0 = *(const float4*)(Ar0 + k0);
        float4 a1 = *(const float4*)(Ar1 + k0);
        float4 w0 = *(const float4*)(Wr0 + k0);
        float4 w1 = *(const float4*)(Wr1 + k0);

        As[c0 + 0][r0] = a0.x; As[c0 + 1][r0] = a0.y;
        As[c0 + 2][r0] = a0.z; As[c0 + 3][r0] = a0.w;
        As[c0 + 0][r1] = a1.x; As[c0 + 1][r1] = a1.y;
        As[c0 + 2][r1] = a1.z; As[c0 + 3][r1] = a1.w;
        Bs[c0 + 0][r0] = w0.x; Bs[c0 + 1][r0] = w0.y;
        Bs[c0 + 2][r0] = w0.z; Bs[c0 + 3][r0] = w0.w;
        Bs[c0 + 0][r1] = w1.x; Bs[c0 + 1][r1] = w1.y;
        Bs[c0 + 2][r1] = w1.z; Bs[c0 + 3][r1] = w1.w;
        __syncthreads();

        mma16(As, Bs, acc, tx, ty);
        __syncthreads();
    }

    const int col = colBase + tx * 8;
    float4 bv0 = *(const float4*)&bias[col];
    float4 bv1 = *(const float4*)&bias[col + 4];
    #pragma unroll
    for (int i = 0; i < 8; i++) {
        size_t row = (size_t)(rowBase + ty * 8 + i);
        float2 c0v = unpack2(acc[i][0]);
        float2 c1v = unpack2(acc[i][1]);
        float2 c2v = unpack2(acc[i][2]);
        float2 c3v = unpack2(acc[i][3]);
        float4 o0 = make_float4(c0v.x + bv0.x, c0v.y + bv0.y,
                                c1v.x + bv0.z, c1v.y + bv0.w);
        float4 o1 = make_float4(c2v.x + bv1.x, c2v.y + bv1.y,
                                c3v.x + bv1.z, c3v.y + bv1.w);
        *(float4*)&C[row * N + col]     = o0;
        *(float4*)&C[row * N + col + 4] = o1;
    }
}

// ---------------------------------------------------------------------------
// KV partial: for (b,h), T-chunk s: KVp[s,bh,d,e] = sum_{t in chunk} K[t,d]*V[t,e]
// ---------------------------------------------------------------------------
__global__ __launch_bounds__(256, 2) void kv_partial()
{
    const int bh = blockIdx.x;             // 0..63
    const int b = bh >> 4, h = bh & 15;
    const int t0 = blockIdx.y * TCHUNK;

    __shared__ __align__(16) float Ks[16][128];
    __shared__ __align__(16) float Vs[16][128];

    const int tid = threadIdx.x;
    const int tx = tid & 15;
    const int ty = tid >> 4;
    const int r0 = tid >> 5;               // 0..7
    const int c0 = (tid & 31) * 4;         // 0..124
    const int r1 = r0 + 8;

    const float* Kb = g_K + ((size_t)b * Tc + t0) * Ec + (size_t)h * Dc;
    const float* Vb = g_V + ((size_t)b * Tc + t0) * Ec + (size_t)h * Dc;

    unsigned long long acc[8][4] = {};

    for (int tt = 0; tt < TCHUNK; tt += 16) {
        *(float4*)&Ks[r0][c0] = *(const float4*)&Kb[(size_t)(tt + r0) * Ec + c0];
        *(float4*)&Ks[r1][c0] = *(const float4*)&Kb[(size_t)(tt + r1) * Ec + c0];
        *(float4*)&Vs[r0][c0] = *(const float4*)&Vb[(size_t)(tt + r0) * Ec + c0];
        *(float4*)&Vs[r1][c0] = *(const float4*)&Vb[(size_t)(tt + r1) * Ec + c0];
        __syncthreads();

        mma16(Ks, Vs, acc, tx, ty);
        __syncthreads();
    }

    float* outp = g_KVp + ((size_t)blockIdx.y * (Bc * Hc) + bh) * (Dc * Dc);
    #pragma unroll
    for (int i = 0; i < 8; i++) {
        int d = ty * 8 + i;
        float2 c0v = unpack2(acc[i][0]);
        float2 c1v = unpack2(acc[i][1]);
        float2 c2v = unpack2(acc[i][2]);
        float2 c3v = unpack2(acc[i][3]);
        *(float4*)&outp[(size_t)d * Dc + tx * 8]     = make_float4(c0v.x, c0v.y, c1v.x, c1v.y);
        *(float4*)&outp[(size_t)d * Dc + tx * 8 + 4] = make_float4(c2v.x, c2v.y, c3v.x, c3v.y);
    }
}

// Deterministic reduce of the 8 partials
__global__ __launch_bounds__(256) void kv_reduce()
{
    const size_t idx = (size_t)blockIdx.x * 256 + threadIdx.x;  // < 64*128*128
    float s = 0.f;
    #pragma unroll
    for (int p = 0; p < TSPLIT; p++)
        s += g_KVp[(size_t)p * (Bc * Hc * Dc * Dc) + idx];
    g_KV[idx] = s;
}

// ---------------------------------------------------------------------------
// attn[b,t,h,:] = scale * Q[b,t,h,:] @ KV[b,h]
// ---------------------------------------------------------------------------
__global__ __launch_bounds__(256, 2) void attn_apply()
{
    const int bh = blockIdx.y;
    const int b = bh >> 4, h = bh & 15;
    const int t0 = blockIdx.x * 128;

    __shared__ __align__(16) float Qs[16][128];   // transposed: Qs[d][t]
    __shared__ __align__(16) float Cs[16][128];   // KV natural: Cs[d][e]

    const int tid = threadIdx.x;
    const int tx = tid & 15;
    const int ty = tid >> 4;

    const int qr0 = tid >> 2, qc0 = (tid & 3) * 4, qr1 = qr0 + 64;
    const int kr0 = tid >> 5, kc0 = (tid & 31) * 4, kr1 = kr0 + 8;

    const float* Qb  = g_Q + ((size_t)b * Tc + t0) * Ec + (size_t)h * Dc;
    const float* KVb = g_KV + (size_t)bh * Dc * Dc;

    unsigned long long acc[8][4] = {};

    for (int k0 = 0; k0 < Dc; k0 += 16) {
        float4 q0 = *(const float4*)&Qb[(size_t)qr0 * Ec + k0 + qc0];
        float4 q1 = *(const float4*)&Qb[(size_t)qr1 * Ec + k0 + qc0];
        Qs[qc0 + 0][qr0] = q0.x; Qs[qc0 + 1][qr0] = q0.y;
        Qs[qc0 + 2][qr0] = q0.z; Qs[qc0 + 3][qr0] = q0.w;
        Qs[qc0 + 0][qr1] = q1.x; Qs[qc0 + 1][qr1] = q1.y;
        Qs[qc0 + 2][qr1] = q1.z; Qs[qc0 + 3][qr1] = q1.w;
        *(float4*)&Cs[kr0][kc0] = *(const float4*)&KVb[(size_t)(k0 + kr0) * Dc + kc0];
        *(float4*)&Cs[kr1][kc0] = *(const float4*)&KVb[(size_t)(k0 + kr1) * Dc + kc0];
        __syncthreads();

        mma16(Qs, Cs, acc, tx, ty);
        __syncthreads();
    }

    const float scale = 0.088388347648318447f;  // 1/sqrt(128)
    float* Ob = g_attn + ((size_t)b * Tc + t0) * Ec + (size_t)h * Dc;
    #pragma unroll
    for (int i = 0; i < 8; i++) {
        size_t row = (size_t)(ty * 8 + i);
        float2 c0v = unpack2(acc[i][0]);
        float2 c1v = unpack2(acc[i][1]);
        float2 c2v = unpack2(acc[i][2]);
        float2 c3v = unpack2(acc[i][3]);
        float4 o0 = make_float4(c0v.x * scale, c0v.y * scale,
                                c1v.x * scale, c1v.y * scale);
        float4 o1 = make_float4(c2v.x * scale, c2v.y * scale,
                                c3v.x * scale, c3v.y * scale);
        *(float4*)&Ob[row * Ec + tx * 8]     = o0;
        *(float4*)&Ob[row * Ec + tx * 8 + 4] = o1;
    }
}

// ---------------------------------------------------------------------------
extern "C" void kernel_launch(void* const* d_in, const int* in_sizes, int n_in,
                              void* d_out, int out_size)
{
    const float* x  = (const float*)d_in[0];
    const float* Wq = (const float*)d_in[1];
    const float* bq = (const float*)d_in[2];
    const float* Wk = (const float*)d_in[3];
    const float* bk = (const float*)d_in[4];
    const float* Wv = (const float*)d_in[5];
    const float* bv = (const float*)d_in[6];
    const float* Wo = (const float*)d_in[7];
    const float* bo = (const float*)d_in[8];
    float* out = (float*)d_out;

    float *Qp, *Kp, *Vp, *Ap;
    cudaGetSymbolAddress((void**)&Qp, g_Q);
    cudaGetSymbolAddress((void**)&Kp, g_K);
    cudaGetSymbolAddress((void**)&Vp, g_V);
    cudaGetSymbolAddress((void**)&Ap, g_attn);

    dim3 blk(256);
    dim3 gP(Ec / 128, NR / 128);   // (16, 128)

    gemm_nt_bias<<<gP, blk>>>(x, Wq, bq, Qp, NR, Ec, Ec);
    gemm_nt_bias<<<gP, blk>>>(x, Wk, bk, Kp, NR, Ec, Ec);
    gemm_nt_bias<<<gP, blk>>>(x, Wv, bv, Vp, NR, Ec, Ec);

    kv_partial<<<dim3(Bc * Hc, TSPLIT), blk>>>();
    kv_reduce<<<(Bc * Hc * Dc * Dc) / 256, blk>>>();

    attn_apply<<<dim3(Tc / 128, Bc * Hc), blk>>>();

    gemm_nt_bias<<<gP, blk>>>(Ap, Wo, bo, out, NR, Ec, Ec);
}

// round 4
// speedup vs baseline: 2.4220x; 2.4220x over previous
#include <cuda_runtime.h>
#include <cuda_bf16.h>
#include <cstdint>

// ---------------------------------------------------------------------------
// Problem constants
// ---------------------------------------------------------------------------
#define Bc 4
#define Tc 4096
#define Ec 2048
#define Hc 16
#define Dc 128
#define NR (Bc * Tc)          // 16384 rows
#define TSPLIT 8
#define TCHUNK (Tc / TSPLIT)  // 512

// ---------------------------------------------------------------------------
// Scratch (device globals: allocation-free per harness rules)
// ---------------------------------------------------------------------------
__device__ float g_Q[(size_t)NR * Ec];
__device__ float g_K[(size_t)NR * Ec];
__device__ float g_V[(size_t)NR * Ec];
__device__ float g_KVp[(size_t)TSPLIT * Bc * Hc * Dc * Dc];
__device__ float g_KV[(size_t)Bc * Hc * Dc * Dc];

__device__ __nv_bfloat16 g_xh[(size_t)NR * Ec];
__device__ __nv_bfloat16 g_xl[(size_t)NR * Ec];
__device__ __nv_bfloat16 g_ah[(size_t)NR * Ec];
__device__ __nv_bfloat16 g_al[(size_t)NR * Ec];
__device__ __nv_bfloat16 g_wh[4][(size_t)Ec * Ec];
__device__ __nv_bfloat16 g_wl[4][(size_t)Ec * Ec];

// ---------------------------------------------------------------------------
// PTX helpers (baseline sm_80+ features only: mma.sync / ldmatrix / cp.async)
// ---------------------------------------------------------------------------
__device__ __forceinline__ uint32_t smem_to_u32(const void* p) {
    uint32_t a;
    asm("{ .reg .u64 t; cvta.to.shared.u64 t, %1; cvt.u32.u64 %0, t; }" : "=r"(a) : "l"(p));
    return a;
}

__device__ __forceinline__ void ldsm_x4(uint32_t (&r)[4], uint32_t addr) {
    asm volatile("ldmatrix.sync.aligned.m8n8.x4.shared.b16 {%0,%1,%2,%3}, [%4];"
        : "=r"(r[0]), "=r"(r[1]), "=r"(r[2]), "=r"(r[3]) : "r"(addr));
}

__device__ __forceinline__ void mma_bf16(float (&c)[4], const uint32_t (&a)[4],
                                         uint32_t b0, uint32_t b1) {
    asm volatile(
        "mma.sync.aligned.m16n8k16.row.col.f32.bf16.bf16.f32 "
        "{%0,%1,%2,%3}, {%4,%5,%6,%7}, {%8,%9}, {%0,%1,%2,%3};"
        : "+f"(c[0]), "+f"(c[1]), "+f"(c[2]), "+f"(c[3])
        : "r"(a[0]), "r"(a[1]), "r"(a[2]), "r"(a[3]), "r"(b0), "r"(b1));
}

__device__ __forceinline__ void cp16(uint32_t s, const void* g) {
    asm volatile("cp.async.cg.shared.global [%0], [%1], 16;" :: "r"(s), "l"(g));
}
#define CP_COMMIT() asm volatile("cp.async.commit_group;" ::: "memory")
#define CP_WAIT(n)  asm volatile("cp.async.wait_group %0;" :: "n"(n) : "memory")

// ---------------------------------------------------------------------------
// HMMA bf16x3 GEMM: C[16384,2048] = (Ah+Al)@(Wh+Wl)^T + bias (3-term split)
// CTA: 128x128 tile, BK=32, 256 threads (8 warps, 2x4 of 64x32 warp tiles).
// smem tile row stride: 40 bf16 = 80B (pad 8) -> conflict-free ldmatrix.
// ---------------------------------------------------------------------------
#define BK 32
#define NCHUNKS (Ec / BK)                 // 64
#define TILE_BYTES (128 * 80)             // 10240 per bf16 tile
#define STAGE_B (4 * TILE_BYTES)          // 40960
#define GEMM_SMEM (2 * STAGE_B)           // 81920

__device__ __forceinline__ void load_stage(uint32_t sm_stage,
                                           const __nv_bfloat16* const (&gp)[4],
                                           int k0, int tid) {
    #pragma unroll
    for (int i = tid; i < 2048; i += 256) {
        const int tile = i >> 9;          // 0..3
        const int j = i & 511;
        const int row = j >> 2;           // 0..127
        const int c16 = j & 3;            // 0..3 (16B chunks of 64B row)
        const void* g = gp[tile] + (size_t)row * Ec + k0 + c16 * 8;
        cp16(sm_stage + tile * TILE_BYTES + row * 80 + c16 * 16, g);
    }
}

__global__ __launch_bounds__(256, 1) void gemm_hmma_x3(
    const __nv_bfloat16* __restrict__ Ah, const __nv_bfloat16* __restrict__ Al,
    const __nv_bfloat16* __restrict__ Wh, const __nv_bfloat16* __restrict__ Wl,
    const float* __restrict__ bias, float* __restrict__ C)
{
    extern __shared__ char smem[];
    const uint32_t smem_u = smem_to_u32(smem);

    const int tid = threadIdx.x;
    const int lane = tid & 31;
    const int wid = tid >> 5;
    const int wm = wid >> 2;              // 0..1 (64 rows each)
    const int wn = wid & 3;               // 0..3 (32 cols each)
    const int rowBase = blockIdx.y * 128;
    const int colBase = blockIdx.x * 128;

    const __nv_bfloat16* gp[4] = {
        Ah + (size_t)rowBase * Ec, Al + (size_t)rowBase * Ec,
        Wh + (size_t)colBase * Ec, Wl + (size_t)colBase * Ec };

    float acc[4][4][4] = {};

    load_stage(smem_u, gp, 0, tid);           CP_COMMIT();
    load_stage(smem_u + STAGE_B, gp, BK, tid); CP_COMMIT();

    // Precomputed ldmatrix base offsets (within a stage)
    const uint32_t aOffBase = (uint32_t)((wm * 64 + (lane & 15)) * 80 + ((lane >> 4) << 4));
    const uint32_t bOffBase = (uint32_t)(2 * TILE_BYTES +
        (wn * 32 + (lane & 7) + ((lane >> 4) & 1) * 8) * 80 + (((lane >> 3) & 1) << 4));

    for (int chunk = 0; chunk < NCHUNKS; chunk++) {
        if (chunk == NCHUNKS - 1) { CP_WAIT(0); } else { CP_WAIT(1); }
        __syncthreads();

        const uint32_t st = smem_u + (chunk & 1) * STAGE_B;

        #pragma unroll
        for (int k16 = 0; k16 < 2; k16++) {
            uint32_t ah[4][4], al[4][4], whf[2][4], wlf[2][4];
            const uint32_t aoff = st + aOffBase + k16 * 32;
            const uint32_t boff = st + bOffBase + k16 * 32;
            #pragma unroll
            for (int i = 0; i < 4; i++) {
                ldsm_x4(ah[i], aoff + i * 16 * 80);
                ldsm_x4(al[i], aoff + TILE_BYTES + i * 16 * 80);
            }
            #pragma unroll
            for (int jj = 0; jj < 2; jj++) {
                ldsm_x4(whf[jj], boff + jj * 16 * 80);
                ldsm_x4(wlf[jj], boff + TILE_BYTES + jj * 16 * 80);
            }
            #pragma unroll
            for (int i = 0; i < 4; i++) {
                #pragma unroll
                for (int j = 0; j < 4; j++) {
                    const int jj = j >> 1, p = (j & 1) * 2;
                    mma_bf16(acc[i][j], ah[i], whf[jj][p], whf[jj][p + 1]);
                    mma_bf16(acc[i][j], ah[i], wlf[jj][p], wlf[jj][p + 1]);
                    mma_bf16(acc[i][j], al[i], whf[jj][p], whf[jj][p + 1]);
                }
            }
        }
        __syncthreads();

        if (chunk + 2 < NCHUNKS)
            load_stage(smem_u + (chunk & 1) * STAGE_B, gp, (chunk + 2) * BK, tid);
        CP_COMMIT();
    }

    // Epilogue
    const int r0 = rowBase + wm * 64 + (lane >> 2);
    const int c0 = colBase + wn * 32 + (lane & 3) * 2;
    #pragma unroll
    for (int j = 0; j < 4; j++) {
        const int col = c0 + j * 8;
        const float2 bv = *(const float2*)&bias[col];
        #pragma unroll
        for (int i = 0; i < 4; i++) {
            const int row = r0 + i * 16;
            float2 o0 = make_float2(acc[i][j][0] + bv.x, acc[i][j][1] + bv.y);
            float2 o1 = make_float2(acc[i][j][2] + bv.x, acc[i][j][3] + bv.y);
            *(float2*)&C[(size_t)row * Ec + col]       = o0;
            *(float2*)&C[(size_t)(row + 8) * Ec + col] = o1;
        }
    }
}

// ---------------------------------------------------------------------------
// fp32 -> (bf16 hi, bf16 lo) split
// ---------------------------------------------------------------------------
__global__ __launch_bounds__(256) void split_bf16(const float* __restrict__ in,
                                                  __nv_bfloat16* __restrict__ hi,
                                                  __nv_bfloat16* __restrict__ lo)
{
    const size_t i = ((size_t)blockIdx.x * 256 + threadIdx.x) * 4;
    float4 v = *(const float4*)(in + i);
    __nv_bfloat16 h0 = __float2bfloat16(v.x), h1 = __float2bfloat16(v.y);
    __nv_bfloat16 h2 = __float2bfloat16(v.z), h3 = __float2bfloat16(v.w);
    __nv_bfloat16 l0 = __float2bfloat16(v.x - __bfloat162float(h0));
    __nv_bfloat16 l1 = __float2bfloat16(v.y - __bfloat162float(h1));
    __nv_bfloat16 l2 = __float2bfloat16(v.z - __bfloat162float(h2));
    __nv_bfloat16 l3 = __float2bfloat16(v.w - __bfloat162float(h3));
    __nv_bfloat162 hp0 = {h0, h1}, hp1 = {h2, h3};
    __nv_bfloat162 lp0 = {l0, l1}, lp1 = {l2, l3};
    *(uint2*)(hi + i) = make_uint2(*(uint32_t*)&hp0, *(uint32_t*)&hp1);
    *(uint2*)(lo + i) = make_uint2(*(uint32_t*)&lp0, *(uint32_t*)&lp1);
}

// ---------------------------------------------------------------------------
// fp32 SIMT attention core (proven round-1 kernels)
// ---------------------------------------------------------------------------
__device__ __forceinline__ void mma16f(const float (*As)[128], const float (*Bs)[128],
                                       float (&acc)[8][8], int tx, int ty) {
    #pragma unroll
    for (int kk = 0; kk < 16; kk++) {
        float a[8], b[8];
        *(float4*)&a[0] = *(const float4*)&As[kk][ty * 8];
        *(float4*)&a[4] = *(const float4*)&As[kk][ty * 8 + 4];
        *(float4*)&b[0] = *(const float4*)&Bs[kk][tx * 8];
        *(float4*)&b[4] = *(const float4*)&Bs[kk][tx * 8 + 4];
        #pragma unroll
        for (int i = 0; i < 8; i++)
            #pragma unroll
            for (int j = 0; j < 8; j++)
                acc[i][j] += a[i] * b[j];
    }
}

__global__ __launch_bounds__(256) void kv_partial()
{
    const int bh = blockIdx.x;
    const int b = bh >> 4, h = bh & 15;
    const int t0 = blockIdx.y * TCHUNK;

    __shared__ __align__(16) float Ks[16][128];
    __shared__ __align__(16) float Vs[16][128];

    const int tid = threadIdx.x;
    const int tx = tid & 15, ty = tid >> 4;
    const int r0 = tid >> 5, c0 = (tid & 31) * 4, r1 = r0 + 8;

    const float* Kb = g_K + ((size_t)b * Tc + t0) * Ec + (size_t)h * Dc;
    const float* Vb = g_V + ((size_t)b * Tc + t0) * Ec + (size_t)h * Dc;

    float acc[8][8] = {};
    for (int tt = 0; tt < TCHUNK; tt += 16) {
        *(float4*)&Ks[r0][c0] = *(const float4*)&Kb[(size_t)(tt + r0) * Ec + c0];
        *(float4*)&Ks[r1][c0] = *(const float4*)&Kb[(size_t)(tt + r1) * Ec + c0];
        *(float4*)&Vs[r0][c0] = *(const float4*)&Vb[(size_t)(tt + r0) * Ec + c0];
        *(float4*)&Vs[r1][c0] = *(const float4*)&Vb[(size_t)(tt + r1) * Ec + c0];
        __syncthreads();
        mma16f(Ks, Vs, acc, tx, ty);
        __syncthreads();
    }

    float* outp = g_KVp + ((size_t)blockIdx.y * (Bc * Hc) + bh) * (Dc * Dc);
    #pragma unroll
    for (int i = 0; i < 8; i++) {
        int d = ty * 8 + i;
        *(float4*)&outp[(size_t)d * Dc + tx * 8]     = *(float4*)&acc[i][0];
        *(float4*)&outp[(size_t)d * Dc + tx * 8 + 4] = *(float4*)&acc[i][4];
    }
}

__global__ __launch_bounds__(256) void kv_reduce()
{
    const size_t idx = (size_t)blockIdx.x * 256 + threadIdx.x;
    float s = 0.f;
    #pragma unroll
    for (int p = 0; p < TSPLIT; p++)
        s += g_KVp[(size_t)p * (Bc * Hc * Dc * Dc) + idx];
    g_KV[idx] = s;
}

// attn = scale * Q @ KV; epilogue fused: writes bf16 hi/lo split directly
__global__ __launch_bounds__(256) void attn_apply_split()
{
    const int bh = blockIdx.y;
    const int b = bh >> 4, h = bh & 15;
    const int t0 = blockIdx.x * 128;

    __shared__ __align__(16) float Qs[16][128];
    __shared__ __align__(16) float Cs[16][128];

    const int tid = threadIdx.x;
    const int tx = tid & 15, ty = tid >> 4;
    const int qr0 = tid >> 2, qc0 = (tid & 3) * 4, qr1 = qr0 + 64;
    const int kr0 = tid >> 5, kc0 = (tid & 31) * 4, kr1 = kr0 + 8;

    const float* Qb  = g_Q + ((size_t)b * Tc + t0) * Ec + (size_t)h * Dc;
    const float* KVb = g_KV + (size_t)bh * Dc * Dc;

    float acc[8][8] = {};
    for (int k0 = 0; k0 < Dc; k0 += 16) {
        float4 q0 = *(const float4*)&Qb[(size_t)qr0 * Ec + k0 + qc0];
        float4 q1 = *(const float4*)&Qb[(size_t)qr1 * Ec + k0 + qc0];
        Qs[qc0 + 0][qr0] = q0.x; Qs[qc0 + 1][qr0] = q0.y;
        Qs[qc0 + 2][qr0] = q0.z; Qs[qc0 + 3][qr0] = q0.w;
        Qs[qc0 + 0][qr1] = q1.x; Qs[qc0 + 1][qr1] = q1.y;
        Qs[qc0 + 2][qr1] = q1.z; Qs[qc0 + 3][qr1] = q1.w;
        *(float4*)&Cs[kr0][kc0] = *(const float4*)&KVb[(size_t)(k0 + kr0) * Dc + kc0];
        *(float4*)&Cs[kr1][kc0] = *(const float4*)&KVb[(size_t)(k0 + kr1) * Dc + kc0];
        __syncthreads();
        mma16f(Qs, Cs, acc, tx, ty);
        __syncthreads();
    }

    const float scale = 0.088388347648318447f;  // 1/sqrt(128)
    __nv_bfloat16* Oh = g_ah + ((size_t)b * Tc + t0) * Ec + (size_t)h * Dc;
    __nv_bfloat16* Ol = g_al + ((size_t)b * Tc + t0) * Ec + (size_t)h * Dc;
    #pragma unroll
    for (int i = 0; i < 8; i++) {
        const size_t off = (size_t)(ty * 8 + i) * Ec + tx * 8;
        __nv_bfloat162 hp[4], lp[4];
        #pragma unroll
        for (int q = 0; q < 4; q++) {
            float v0 = acc[i][q * 2] * scale;
            float v1 = acc[i][q * 2 + 1] * scale;
            __nv_bfloat16 h0 = __float2bfloat16(v0);
            __nv_bfloat16 h1 = __float2bfloat16(v1);
            hp[q] = {h0, h1};
            lp[q] = {__float2bfloat16(v0 - __bfloat162float(h0)),
                     __float2bfloat16(v1 - __bfloat162float(h1))};
        }
        *(uint4*)(Oh + off) = *(uint4*)hp;
        *(uint4*)(Ol + off) = *(uint4*)lp;
    }
}

// ---------------------------------------------------------------------------
extern "C" void kernel_launch(void* const* d_in, const int* in_sizes, int n_in,
                              void* d_out, int out_size)
{
    const float* x  = (const float*)d_in[0];
    const float* Wq = (const float*)d_in[1];
    const float* bq = (const float*)d_in[2];
    const float* Wk = (const float*)d_in[3];
    const float* bk = (const float*)d_in[4];
    const float* Wv = (const float*)d_in[5];
    const float* bv = (const float*)d_in[6];
    const float* Wo = (const float*)d_in[7];
    const float* bo = (const float*)d_in[8];
    float* out = (float*)d_out;

    float *Qp, *Kp, *Vp;
    cudaGetSymbolAddress((void**)&Qp, g_Q);
    cudaGetSymbolAddress((void**)&Kp, g_K);
    cudaGetSymbolAddress((void**)&Vp, g_V);
    __nv_bfloat16 *xh, *xl, *ah, *al, *wh, *wl;
    cudaGetSymbolAddress((void**)&xh, g_xh);
    cudaGetSymbolAddress((void**)&xl, g_xl);
    cudaGetSymbolAddress((void**)&ah, g_ah);
    cudaGetSymbolAddress((void**)&al, g_al);
    cudaGetSymbolAddress((void**)&wh, g_wh);
    cudaGetSymbolAddress((void**)&wl, g_wl);

    static bool attr_set = false;
    if (!attr_set) {
        cudaFuncSetAttribute(gemm_hmma_x3,
                             cudaFuncAttributeMaxDynamicSharedMemorySize, GEMM_SMEM);
        attr_set = true;
    }

    const size_t WSZ = (size_t)Ec * Ec;
    dim3 blk(256);

    // Splits
    split_bf16<<<(unsigned)((size_t)NR * Ec / 4 / 256), blk>>>(x, xh, xl);
    split_bf16<<<(unsigned)(WSZ / 4 / 256), blk>>>(Wq, wh + 0 * WSZ, wl + 0 * WSZ);
    split_bf16<<<(unsigned)(WSZ / 4 / 256), blk>>>(Wk, wh + 1 * WSZ, wl + 1 * WSZ);
    split_bf16<<<(unsigned)(WSZ / 4 / 256), blk>>>(Wv, wh + 2 * WSZ, wl + 2 * WSZ);
    split_bf16<<<(unsigned)(WSZ / 4 / 256), blk>>>(Wo, wh + 3 * WSZ, wl + 3 * WSZ);

    // Projections on tensor cores (HMMA bf16x3)
    dim3 gG(Ec / 128, NR / 128);   // (16, 128)
    gemm_hmma_x3<<<gG, blk, GEMM_SMEM>>>(xh, xl, wh + 0 * WSZ, wl + 0 * WSZ, bq, Qp);
    gemm_hmma_x3<<<gG, blk, GEMM_SMEM>>>(xh, xl, wh + 1 * WSZ, wl + 1 * WSZ, bk, Kp);
    gemm_hmma_x3<<<gG, blk, GEMM_SMEM>>>(xh, xl, wh + 2 * WSZ, wl + 2 * WSZ, bv, Vp);

    // Linear attention core (fp32 SIMT), attn epilogue fused with bf16 split
    kv_partial<<<dim3(Bc * Hc, TSPLIT), blk>>>();
    kv_reduce<<<(Bc * Hc * Dc * Dc) / 256, blk>>>();
    attn_apply_split<<<dim3(Tc / 128, Bc * Hc), blk>>>();

    // Output projection
    gemm_hmma_x3<<<gG, blk, GEMM_SMEM>>>(ah, al, wh + 3 * WSZ, wl + 3 * WSZ, bo, out);
}

// round 5
// speedup vs baseline: 2.7844x; 1.1496x over previous
#include <cuda_runtime.h>
#include <cuda_bf16.h>
#include <cstdint>

// ---------------------------------------------------------------------------
// Problem constants
// ---------------------------------------------------------------------------
#define Bc 4
#define Tc 4096
#define Ec 2048
#define Hc 16
#define Dc 128
#define NR (Bc * Tc)          // 16384 rows
#define TSPLIT 8
#define TCHUNK (Tc / TSPLIT)  // 512

// ---------------------------------------------------------------------------
// Scratch (device globals: allocation-free per harness rules)
// ---------------------------------------------------------------------------
__device__ float g_Q[(size_t)NR * Ec];
__device__ float g_K[(size_t)NR * Ec];
__device__ float g_V[(size_t)NR * Ec];
__device__ float g_KVp[(size_t)TSPLIT * Bc * Hc * Dc * Dc];
__device__ float g_KV[(size_t)Bc * Hc * Dc * Dc];

__device__ __nv_bfloat16 g_xh[(size_t)NR * Ec];
__device__ __nv_bfloat16 g_xl[(size_t)NR * Ec];
__device__ __nv_bfloat16 g_ah[(size_t)NR * Ec];
__device__ __nv_bfloat16 g_al[(size_t)NR * Ec];
__device__ __nv_bfloat16 g_wh[4][(size_t)Ec * Ec];
__device__ __nv_bfloat16 g_wl[4][(size_t)Ec * Ec];

// ---------------------------------------------------------------------------
// PTX helpers (baseline sm_80+ features only: mma.sync / ldmatrix / cp.async)
// ---------------------------------------------------------------------------
__device__ __forceinline__ uint32_t smem_to_u32(const void* p) {
    uint32_t a;
    asm("{ .reg .u64 t; cvta.to.shared.u64 t, %1; cvt.u32.u64 %0, t; }" : "=r"(a) : "l"(p));
    return a;
}

__device__ __forceinline__ void ldsm_x4(uint32_t (&r)[4], uint32_t addr) {
    asm volatile("ldmatrix.sync.aligned.m8n8.x4.shared.b16 {%0,%1,%2,%3}, [%4];"
        : "=r"(r[0]), "=r"(r[1]), "=r"(r[2]), "=r"(r[3]) : "r"(addr));
}

__device__ __forceinline__ void mma_bf16(float (&c)[4], const uint32_t (&a)[4],
                                         uint32_t b0, uint32_t b1) {
    asm volatile(
        "mma.sync.aligned.m16n8k16.row.col.f32.bf16.bf16.f32 "
        "{%0,%1,%2,%3}, {%4,%5,%6,%7}, {%8,%9}, {%0,%1,%2,%3};"
        : "+f"(c[0]), "+f"(c[1]), "+f"(c[2]), "+f"(c[3])
        : "r"(a[0]), "r"(a[1]), "r"(a[2]), "r"(a[3]), "r"(b0), "r"(b1));
}

__device__ __forceinline__ void cp16(uint32_t s, const void* g) {
    asm volatile("cp.async.cg.shared.global [%0], [%1], 16;" :: "r"(s), "l"(g));
}
#define CP_COMMIT() asm volatile("cp.async.commit_group;" ::: "memory")
#define CP_WAIT(n)  asm volatile("cp.async.wait_group %0;" :: "n"(n) : "memory")

// ---------------------------------------------------------------------------
// HMMA bf16x3 GEMM: C[16384,2048] = (Ah+Al)@(Wh+Wl)^T + bias (3-term split)
// CTA: 128x128 tile, BK=32, 256 threads (8 warps, 2x4 of 64x32 warp tiles).
// 4-stage cp.async pipeline, ONE __syncthreads per chunk.
// smem tile row stride: 40 bf16 = 80B (pad 8) -> conflict-free ldmatrix.
// ---------------------------------------------------------------------------
#define BK 32
#define NCHUNKS (Ec / BK)                 // 64
#define NSTAGE 4
#define TILE_BYTES (128 * 80)             // 10240 per bf16 tile
#define STAGE_B (4 * TILE_BYTES)          // 40960
#define GEMM_SMEM (NSTAGE * STAGE_B)      // 163840

__device__ __forceinline__ void load_stage(uint32_t sm_stage,
                                           const __nv_bfloat16* const (&gp)[4],
                                           int k0, int tid) {
    #pragma unroll
    for (int i = tid; i < 2048; i += 256) {
        const int tile = i >> 9;          // 0..3
        const int j = i & 511;
        const int row = j >> 2;           // 0..127
        const int c16 = j & 3;            // 0..3 (16B chunks of 64B row)
        const void* g = gp[tile] + (size_t)row * Ec + k0 + c16 * 8;
        cp16(sm_stage + tile * TILE_BYTES + row * 80 + c16 * 16, g);
    }
}

__global__ __launch_bounds__(256, 1) void gemm_hmma_x3(
    const __nv_bfloat16* __restrict__ Ah, const __nv_bfloat16* __restrict__ Al,
    const __nv_bfloat16* __restrict__ Wh, const __nv_bfloat16* __restrict__ Wl,
    const float* __restrict__ bias, float* __restrict__ C)
{
    extern __shared__ char smem[];
    const uint32_t smem_u = smem_to_u32(smem);

    const int tid = threadIdx.x;
    const int lane = tid & 31;
    const int wid = tid >> 5;
    const int wm = wid >> 2;              // 0..1 (64 rows each)
    const int wn = wid & 3;               // 0..3 (32 cols each)
    const int rowBase = blockIdx.y * 128;
    const int colBase = blockIdx.x * 128;

    const __nv_bfloat16* gp[4] = {
        Ah + (size_t)rowBase * Ec, Al + (size_t)rowBase * Ec,
        Wh + (size_t)colBase * Ec, Wl + (size_t)colBase * Ec };

    float acc[4][4][4] = {};

    // Prologue: prefetch 3 stages
    load_stage(smem_u + 0 * STAGE_B, gp, 0 * BK, tid); CP_COMMIT();
    load_stage(smem_u + 1 * STAGE_B, gp, 1 * BK, tid); CP_COMMIT();
    load_stage(smem_u + 2 * STAGE_B, gp, 2 * BK, tid); CP_COMMIT();

    // Precomputed ldmatrix base offsets (within a stage)
    const uint32_t aOffBase = (uint32_t)((wm * 64 + (lane & 15)) * 80 + ((lane >> 4) << 4));
    const uint32_t bOffBase = (uint32_t)(2 * TILE_BYTES +
        (wn * 32 + (lane & 7) + ((lane >> 4) & 1) * 8) * 80 + (((lane >> 3) & 1) << 4));

    for (int chunk = 0; chunk < NCHUNKS; chunk++) {
        CP_WAIT(2);                // chunk's stage is resident
        __syncthreads();           // single barrier per chunk

        const uint32_t st = smem_u + (chunk & (NSTAGE - 1)) * STAGE_B;

        #pragma unroll
        for (int k16 = 0; k16 < 2; k16++) {
            uint32_t ah[4][4], al[4][4], whf[2][4], wlf[2][4];
            const uint32_t aoff = st + aOffBase + k16 * 32;
            const uint32_t boff = st + bOffBase + k16 * 32;
            #pragma unroll
            for (int i = 0; i < 4; i++) {
                ldsm_x4(ah[i], aoff + i * 16 * 80);
                ldsm_x4(al[i], aoff + TILE_BYTES + i * 16 * 80);
            }
            #pragma unroll
            for (int jj = 0; jj < 2; jj++) {
                ldsm_x4(whf[jj], boff + jj * 16 * 80);
                ldsm_x4(wlf[jj], boff + TILE_BYTES + jj * 16 * 80);
            }
            #pragma unroll
            for (int i = 0; i < 4; i++) {
                #pragma unroll
                for (int j = 0; j < 4; j++) {
                    const int jj = j >> 1, p = (j & 1) * 2;
                    mma_bf16(acc[i][j], ah[i], whf[jj][p], whf[jj][p + 1]);
                    mma_bf16(acc[i][j], ah[i], wlf[jj][p], wlf[jj][p + 1]);
                    mma_bf16(acc[i][j], al[i], whf[jj][p], whf[jj][p + 1]);
                }
            }
        }

        // Prefetch chunk+3 into the stage freed at chunk-1 (safe: barrier above
        // ordered it after all warps finished chunk-1's reads).
        if (chunk + 3 < NCHUNKS)
            load_stage(smem_u + ((chunk + 3) & (NSTAGE - 1)) * STAGE_B, gp,
                       (chunk + 3) * BK, tid);
        CP_COMMIT();
    }

    // Epilogue
    const int r0 = rowBase + wm * 64 + (lane >> 2);
    const int c0 = colBase + wn * 32 + (lane & 3) * 2;
    #pragma unroll
    for (int j = 0; j < 4; j++) {
        const int col = c0 + j * 8;
        const float2 bv = *(const float2*)&bias[col];
        #pragma unroll
        for (int i = 0; i < 4; i++) {
            const int row = r0 + i * 16;
            float2 o0 = make_float2(acc[i][j][0] + bv.x, acc[i][j][1] + bv.y);
            float2 o1 = make_float2(acc[i][j][2] + bv.x, acc[i][j][3] + bv.y);
            *(float2*)&C[(size_t)row * Ec + col]       = o0;
            *(float2*)&C[(size_t)(row + 8) * Ec + col] = o1;
        }
    }
}

// ---------------------------------------------------------------------------
// fp32 -> (bf16 hi, bf16 lo) split
// ---------------------------------------------------------------------------
__global__ __launch_bounds__(256) void split_bf16(const float* __restrict__ in,
                                                  __nv_bfloat16* __restrict__ hi,
                                                  __nv_bfloat16* __restrict__ lo)
{
    const size_t i = ((size_t)blockIdx.x * 256 + threadIdx.x) * 4;
    float4 v = *(const float4*)(in + i);
    __nv_bfloat16 h0 = __float2bfloat16(v.x), h1 = __float2bfloat16(v.y);
    __nv_bfloat16 h2 = __float2bfloat16(v.z), h3 = __float2bfloat16(v.w);
    __nv_bfloat16 l0 = __float2bfloat16(v.x - __bfloat162float(h0));
    __nv_bfloat16 l1 = __float2bfloat16(v.y - __bfloat162float(h1));
    __nv_bfloat16 l2 = __float2bfloat16(v.z - __bfloat162float(h2));
    __nv_bfloat16 l3 = __float2bfloat16(v.w - __bfloat162float(h3));
    __nv_bfloat162 hp0 = {h0, h1}, hp1 = {h2, h3};
    __nv_bfloat162 lp0 = {l0, l1}, lp1 = {l2, l3};
    *(uint2*)(hi + i) = make_uint2(*(uint32_t*)&hp0, *(uint32_t*)&hp1);
    *(uint2*)(lo + i) = make_uint2(*(uint32_t*)&lp0, *(uint32_t*)&lp1);
}

// ---------------------------------------------------------------------------
// fp32 SIMT attention core (proven round-1 kernels)
// ---------------------------------------------------------------------------
__device__ __forceinline__ void mma16f(const float (*As)[128], const float (*Bs)[128],
                                       float (&acc)[8][8], int tx, int ty) {
    #pragma unroll
    for (int kk = 0; kk < 16; kk++) {
        float a[8], b[8];
        *(float4*)&a[0] = *(const float4*)&As[kk][ty * 8];
        *(float4*)&a[4] = *(const float4*)&As[kk][ty * 8 + 4];
        *(float4*)&b[0] = *(const float4*)&Bs[kk][tx * 8];
        *(float4*)&b[4] = *(const float4*)&Bs[kk][tx * 8 + 4];
        #pragma unroll
        for (int i = 0; i < 8; i++)
            #pragma unroll
            for (int j = 0; j < 8; j++)
                acc[i][j] += a[i] * b[j];
    }
}

__global__ __launch_bounds__(256) void kv_partial()
{
    const int bh = blockIdx.x;
    const int b = bh >> 4, h = bh & 15;
    const int t0 = blockIdx.y * TCHUNK;

    __shared__ __align__(16) float Ks[16][128];
    __shared__ __align__(16) float Vs[16][128];

    const int tid = threadIdx.x;
    const int tx = tid & 15, ty = tid >> 4;
    const int r0 = tid >> 5, c0 = (tid & 31) * 4, r1 = r0 + 8;

    const float* Kb = g_K + ((size_t)b * Tc + t0) * Ec + (size_t)h * Dc;
    const float* Vb = g_V + ((size_t)b * Tc + t0) * Ec + (size_t)h * Dc;

    float acc[8][8] = {};
    for (int tt = 0; tt < TCHUNK; tt += 16) {
        *(float4*)&Ks[r0][c0] = *(const float4*)&Kb[(size_t)(tt + r0) * Ec + c0];
        *(float4*)&Ks[r1][c0] = *(const float4*)&Kb[(size_t)(tt + r1) * Ec + c0];
        *(float4*)&Vs[r0][c0] = *(const float4*)&Vb[(size_t)(tt + r0) * Ec + c0];
        *(float4*)&Vs[r1][c0] = *(const float4*)&Vb[(size_t)(tt + r1) * Ec + c0];
        __syncthreads();
        mma16f(Ks, Vs, acc, tx, ty);
        __syncthreads();
    }

    float* outp = g_KVp + ((size_t)blockIdx.y * (Bc * Hc) + bh) * (Dc * Dc);
    #pragma unroll
    for (int i = 0; i < 8; i++) {
        int d = ty * 8 + i;
        *(float4*)&outp[(size_t)d * Dc + tx * 8]     = *(float4*)&acc[i][0];
        *(float4*)&outp[(size_t)d * Dc + tx * 8 + 4] = *(float4*)&acc[i][4];
    }
}

__global__ __launch_bounds__(256) void kv_reduce()
{
    const size_t idx = (size_t)blockIdx.x * 256 + threadIdx.x;
    float s = 0.f;
    #pragma unroll
    for (int p = 0; p < TSPLIT; p++)
        s += g_KVp[(size_t)p * (Bc * Hc * Dc * Dc) + idx];
    g_KV[idx] = s;
}

// attn = scale * Q @ KV; epilogue fused: writes bf16 hi/lo split directly
__global__ __launch_bounds__(256) void attn_apply_split()
{
    const int bh = blockIdx.y;
    const int b = bh >> 4, h = bh & 15;
    const int t0 = blockIdx.x * 128;

    __shared__ __align__(16) float Qs[16][128];
    __shared__ __align__(16) float Cs[16][128];

    const int tid = threadIdx.x;
    const int tx = tid & 15, ty = tid >> 4;
    const int qr0 = tid >> 2, qc0 = (tid & 3) * 4, qr1 = qr0 + 64;
    const int kr0 = tid >> 5, kc0 = (tid & 31) * 4, kr1 = kr0 + 8;

    const float* Qb  = g_Q + ((size_t)b * Tc + t0) * Ec + (size_t)h * Dc;
    const float* KVb = g_KV + (size_t)bh * Dc * Dc;

    float acc[8][8] = {};
    for (int k0 = 0; k0 < Dc; k0 += 16) {
        float4 q0 = *(const float4*)&Qb[(size_t)qr0 * Ec + k0 + qc0];
        float4 q1 = *(const float4*)&Qb[(size_t)qr1 * Ec + k0 + qc0];
        Qs[qc0 + 0][qr0] = q0.x; Qs[qc0 + 1][qr0] = q0.y;
        Qs[qc0 + 2][qr0] = q0.z; Qs[qc0 + 3][qr0] = q0.w;
        Qs[qc0 + 0][qr1] = q1.x; Qs[qc0 + 1][qr1] = q1.y;
        Qs[qc0 + 2][qr1] = q1.z; Qs[qc0 + 3][qr1] = q1.w;
        *(float4*)&Cs[kr0][kc0] = *(const float4*)&KVb[(size_t)(k0 + kr0) * Dc + kc0];
        *(float4*)&Cs[kr1][kc0] = *(const float4*)&KVb[(size_t)(k0 + kr1) * Dc + kc0];
        __syncthreads();
        mma16f(Qs, Cs, acc, tx, ty);
        __syncthreads();
    }

    const float scale = 0.088388347648318447f;  // 1/sqrt(128)
    __nv_bfloat16* Oh = g_ah + ((size_t)b * Tc + t0) * Ec + (size_t)h * Dc;
    __nv_bfloat16* Ol = g_al + ((size_t)b * Tc + t0) * Ec + (size_t)h * Dc;
    #pragma unroll
    for (int i = 0; i < 8; i++) {
        const size_t off = (size_t)(ty * 8 + i) * Ec + tx * 8;
        __nv_bfloat162 hp[4], lp[4];
        #pragma unroll
        for (int q = 0; q < 4; q++) {
            float v0 = acc[i][q * 2] * scale;
            float v1 = acc[i][q * 2 + 1] * scale;
            __nv_bfloat16 h0 = __float2bfloat16(v0);
            __nv_bfloat16 h1 = __float2bfloat16(v1);
            hp[q] = {h0, h1};
            lp[q] = {__float2bfloat16(v0 - __bfloat162float(h0)),
                     __float2bfloat16(v1 - __bfloat162float(h1))};
        }
        *(uint4*)(Oh + off) = *(uint4*)hp;
        *(uint4*)(Ol + off) = *(uint4*)lp;
    }
}

// ---------------------------------------------------------------------------
extern "C" void kernel_launch(void* const* d_in, const int* in_sizes, int n_in,
                              void* d_out, int out_size)
{
    const float* x  = (const float*)d_in[0];
    const float* Wq = (const float*)d_in[1];
    const float* bq = (const float*)d_in[2];
    const float* Wk = (const float*)d_in[3];
    const float* bk = (const float*)d_in[4];
    const float* Wv = (const float*)d_in[5];
    const float* bv = (const float*)d_in[6];
    const float* Wo = (const float*)d_in[7];
    const float* bo = (const float*)d_in[8];
    float* out = (float*)d_out;

    float *Qp, *Kp, *Vp;
    cudaGetSymbolAddress((void**)&Qp, g_Q);
    cudaGetSymbolAddress((void**)&Kp, g_K);
    cudaGetSymbolAddress((void**)&Vp, g_V);
    __nv_bfloat16 *xh, *xl, *ah, *al, *wh, *wl;
    cudaGetSymbolAddress((void**)&xh, g_xh);
    cudaGetSymbolAddress((void**)&xl, g_xl);
    cudaGetSymbolAddress((void**)&ah, g_ah);
    cudaGetSymbolAddress((void**)&al, g_al);
    cudaGetSymbolAddress((void**)&wh, g_wh);
    cudaGetSymbolAddress((void**)&wl, g_wl);

    static bool attr_set = false;
    if (!attr_set) {
        cudaFuncSetAttribute(gemm_hmma_x3,
                             cudaFuncAttributeMaxDynamicSharedMemorySize, GEMM_SMEM);
        attr_set = true;
    }

    const size_t WSZ = (size_t)Ec * Ec;
    dim3 blk(256);

    // Splits
    split_bf16<<<(unsigned)((size_t)NR * Ec / 4 / 256), blk>>>(x, xh, xl);
    split_bf16<<<(unsigned)(WSZ / 4 / 256), blk>>>(Wq, wh + 0 * WSZ, wl + 0 * WSZ);
    split_bf16<<<(unsigned)(WSZ / 4 / 256), blk>>>(Wk, wh + 1 * WSZ, wl + 1 * WSZ);
    split_bf16<<<(unsigned)(WSZ / 4 / 256), blk>>>(Wv, wh + 2 * WSZ, wl + 2 * WSZ);
    split_bf16<<<(unsigned)(WSZ / 4 / 256), blk>>>(Wo, wh + 3 * WSZ, wl + 3 * WSZ);

    // Projections on tensor cores (HMMA bf16x3)
    dim3 gG(Ec / 128, NR / 128);   // (16, 128)
    gemm_hmma_x3<<<gG, blk, GEMM_SMEM>>>(xh, xl, wh + 0 * WSZ, wl + 0 * WSZ, bq, Qp);
    gemm_hmma_x3<<<gG, blk, GEMM_SMEM>>>(xh, xl, wh + 1 * WSZ, wl + 1 * WSZ, bk, Kp);
    gemm_hmma_x3<<<gG, blk, GEMM_SMEM>>>(xh, xl, wh + 2 * WSZ, wl + 2 * WSZ, bv, Vp);

    // Linear attention core (fp32 SIMT), attn epilogue fused with bf16 split
    kv_partial<<<dim3(Bc * Hc, TSPLIT), blk>>>();
    kv_reduce<<<(Bc * Hc * Dc * Dc) / 256, blk>>>();
    attn_apply_split<<<dim3(Tc / 128, Bc * Hc), blk>>>();

    // Output projection
    gemm_hmma_x3<<<gG, blk, GEMM_SMEM>>>(ah, al, wh + 3 * WSZ, wl + 3 * WSZ, bo, out);
}